// round 8
// baseline (speedup 1.0000x reference)
#include <cuda_runtime.h>
#include <cuda_fp16.h>
#include <stdint.h>

#define TOKENS 8192
#define IN_F   4096
#define OUT_F  11008
#define KK     8192          // concatenated K: [hi 4096 | lo 4096]

// ---------------- scratch (device globals; no allocation allowed) -----------
__device__ __align__(16) float  g_sa[IN_F];
__device__ float g_S;
__device__ __align__(16) int8_t g_aq[(size_t)TOKENS * KK];   // 64 MB  [a8 | a4]
__device__ __align__(16) int8_t g_bq[(size_t)OUT_F  * KK];   // 88 MB  [16*qw | qw]
__device__ __align__(16) float  g_swf[OUT_F];
__device__ int g_sw_mode;     // 0 = f16, 1 = f32, 2 = bf16
__device__ int g_pw_is_i32;   // packed_w delivered as int32-per-byte

// ============================================================================
// Kernel 0: input dtype detection (harness upcasts f16 and uint8 inputs)
// ============================================================================
__global__ void detect_kernel(const void* __restrict__ s_w, const void* __restrict__ pw) {
    bool bf_ok = true;
    const uint16_t* u16 = (const uint16_t*)s_w;
#pragma unroll
    for (int i = 0; i < 16; ++i) {
        float v = __uint_as_float(((uint32_t)u16[i]) << 16);
        bf_ok = bf_ok && isfinite(v) && (v > 1e-4f) && (v < 0.5f);
    }
    bool f32_ok = true;
    const float* f = (const float*)s_w;
#pragma unroll
    for (int i = 0; i < 8; ++i) {
        float v = f[i];
        f32_ok = f32_ok && isfinite(v) && (v > 1e-4f) && (v < 0.5f);
    }
    g_sw_mode = bf_ok ? 2 : (f32_ok ? 1 : 0);

    const int* pi = (const int*)pw;
    bool i32_ok = true;
#pragma unroll
    for (int i = 0; i < 64; ++i) { int v = pi[i]; i32_ok = i32_ok && (v >= 0) && (v <= 255); }
    g_pw_is_i32 = i32_ok ? 1 : 0;
}

// ============================================================================
// Kernel 1: per-column 0.999 quantile of |x| -> s_a
// ============================================================================
__global__ void quantile_kernel(const float* __restrict__ x) {
    __shared__ float tops[256][10];
    const int t = threadIdx.x, cl = t & 63, chunk = t >> 6;
    const int col = blockIdx.x * 64 + cl;
    const float* p = x + (size_t)chunk * 2048 * IN_F + col;

    float tt[10];
#pragma unroll
    for (int i = 0; i < 10; ++i) tt[i] = -1.0f;
#pragma unroll 4
    for (int r = 0; r < 2048; ++r) {
        float v = fabsf(p[(size_t)r * IN_F]);
        if (v > tt[9]) {
            tt[9] = v;
#pragma unroll
            for (int j = 9; j > 0; --j)
                if (tt[j] > tt[j - 1]) { float tmp = tt[j - 1]; tt[j - 1] = tt[j]; tt[j] = tmp; }
        }
    }
#pragma unroll
    for (int i = 0; i < 10; ++i) tops[t][i] = tt[i];
    __syncthreads();

    if (chunk == 0) {
        int pi[4] = {0, 0, 0, 0};
        float v9th = 0.f, v10th = 0.f;
        for (int i = 0; i < 10; ++i) {
            int best = 0; float bv = tops[cl][pi[0]];
#pragma unroll
            for (int j = 1; j < 4; ++j) {
                float c = tops[cl + 64 * j][pi[j]];
                if (c > bv) { bv = c; best = j; }
            }
            pi[best]++;
            if (i == 8) v9th = bv;
            if (i == 9) v10th = bv;
        }
        float pos = 0.999f * 8191.0f;
        float qv  = v10th * (8183.0f - pos) + v9th * (pos - 8182.0f);
        float s = fmaxf(qv, 1e-6f) / 127.0f;
        s = fmaxf(s, 1e-6f);
        s = __half2float(__float2half_rn(s));
        g_sa[col] = s;
    }
}

// ============================================================================
// Kernel 1b: S = max(s_a)
// ============================================================================
__global__ void smax_kernel() {
    __shared__ float red[256];
    float m = 0.f;
    for (int i = threadIdx.x; i < IN_F; i += 256) m = fmaxf(m, g_sa[i]);
    red[threadIdx.x] = m;
    __syncthreads();
    for (int s = 128; s > 0; s >>= 1) {
        if (threadIdx.x < s) red[threadIdx.x] = fmaxf(red[threadIdx.x], red[threadIdx.x + s]);
        __syncthreads();
    }
    if (threadIdx.x == 0) g_S = red[0];
}

// ============================================================================
// Kernel 2: fake-quant x -> split int8 pieces a8 (coarse) + a4 (fine/16)
//   value represented = S*(a8 + a4/16); |error| <= S/32.
// ============================================================================
__global__ void quant_x_kernel(const float* __restrict__ x) {
    size_t i = (size_t)blockIdx.x * blockDim.x + threadIdx.x;   // 8-elem group
    size_t base = i * 8;
    int row = (int)(base >> 12);
    int kb  = (int)(base & 4095);
    float Sinv = 1.f / g_S;

    const float4* xp = (const float4*)(x + base);
    float4 x0 = xp[0], x1 = xp[1];
    const float4* sp = (const float4*)(g_sa + kb);
    float4 s0 = sp[0], s1 = sp[1];

    float xs[8] = {x0.x, x0.y, x0.z, x0.w, x1.x, x1.y, x1.z, x1.w};
    float ss[8] = {s0.x, s0.y, s0.z, s0.w, s1.x, s1.y, s1.z, s1.w};

    uint32_t hi0 = 0, hi1 = 0, lo0 = 0, lo1 = 0;
#pragma unroll
    for (int j = 0; j < 8; ++j) {
        float q = fminf(fmaxf(rintf(xs[j] / ss[j]), -127.f), 127.f);
        float t = q * ss[j] * Sinv;          // in [-127, 127]
        float h = rintf(t);
        int   l = (int)rintf((t - h) * 16.f);
        l = (l > 7) ? 7 : ((l < -8) ? -8 : l);
        uint32_t hb = (uint32_t)((int)h & 0xFF);
        uint32_t lb = (uint32_t)(l & 0xFF);
        if (j < 4) { hi0 |= hb << (8 * j);      lo0 |= lb << (8 * j); }
        else       { hi1 |= hb << (8 * (j - 4)); lo1 |= lb << (8 * (j - 4)); }
    }
    int8_t* arow = g_aq + (size_t)row * KK;
    *reinterpret_cast<uint2*>(arow + kb)        = make_uint2(hi0, hi1);
    *reinterpret_cast<uint2*>(arow + 4096 + kb) = make_uint2(lo0, lo1);
}

// ============================================================================
// Kernel 3: weights -> B' = [16*q_w | q_w] int8. One thread = 4 packed bytes.
// ============================================================================
__global__ void prep_w_kernel(const void* __restrict__ pw) {
    size_t i = (size_t)blockIdx.x * blockDim.x + threadIdx.x;   // 4-byte group
    int b4[4];
    if (g_pw_is_i32) {
        int4 v = reinterpret_cast<const int4*>(pw)[i];
        b4[0] = v.x & 0xFF; b4[1] = v.y & 0xFF; b4[2] = v.z & 0xFF; b4[3] = v.w & 0xFF;
    } else {
        uint32_t w = reinterpret_cast<const uint32_t*>(pw)[i];
        b4[0] = w & 0xFF; b4[1] = (w >> 8) & 0xFF; b4[2] = (w >> 16) & 0xFF; b4[3] = (w >> 24) & 0xFF;
    }
    size_t o  = i >> 9;                       // 512 groups per output row
    int    kb = (int)(i & 511) * 8;           // k offset within row

    uint32_t hi0 = 0, hi1 = 0, lo0 = 0, lo1 = 0;
#pragma unroll
    for (int j = 0; j < 4; ++j) {
        int b = b4[j];
        int l = ((b & 15) ^ 8) - 8;           // signed low nibble  (k even)
        int h = ((b >> 4) ^ 8) - 8;           // signed high nibble (k odd)
        uint32_t l16 = (uint32_t)((16 * l) & 0xFF), h16 = (uint32_t)((16 * h) & 0xFF);
        uint32_t lu  = (uint32_t)(l & 0xFF),        hu  = (uint32_t)(h & 0xFF);
        if (j < 2) { hi0 |= l16 << (16 * j) | h16 << (16 * j + 8);
                     lo0 |= lu  << (16 * j) | hu  << (16 * j + 8); }
        else       { hi1 |= l16 << (16 * (j - 2)) | h16 << (16 * (j - 2) + 8);
                     lo1 |= lu  << (16 * (j - 2)) | hu  << (16 * (j - 2) + 8); }
    }
    int8_t* brow = g_bq + o * KK;
    *reinterpret_cast<uint2*>(brow + kb)        = make_uint2(hi0, hi1);
    *reinterpret_cast<uint2*>(brow + 4096 + kb) = make_uint2(lo0, lo1);
}

// Kernel 3b: s_w -> float
__global__ void swf_kernel(const void* __restrict__ s_w) {
    int i = blockIdx.x * blockDim.x + threadIdx.x;
    int mode = g_sw_mode;
    float v;
    if (mode == 1)      v = ((const float*)s_w)[i];
    else if (mode == 2) v = __uint_as_float(((uint32_t)((const uint16_t*)s_w)[i]) << 16);
    else                v = __half2float(((const __half*)s_w)[i]);
    g_swf[i] = v;
}

// ============================================================================
// Kernel 4: int8 GEMM  acc = A'[8192,8192] @ B'[11008,8192]^T (s32)
//   y = (S/16)*s_w*acc + bias.
//   CTA 128x256, warp 64x64, K-chunk 64B, 4-stage cp.async,
//   ldmatrix(b16 on byte tiles) + mma.m16n8k32.s8.
// ============================================================================
#define GBM 128
#define GBN 256
#define GBK 64
#define AST 80                     // byte stride per 64B row (conflict-free mod 128)
#define ASTG (GBM * AST)           // 10240
#define BSTG (GBN * AST)           // 20480
#define STG  (ASTG + BSTG)         // 30720
#define NSTG 4
#define NCH  (KK / GBK)            // 128
#define NT_N (OUT_F / GBN)         // 43
#define BAND 16

extern __shared__ __align__(16) uint8_t smem[];

__device__ __forceinline__ void cp16(uint32_t dst, const void* src) {
    asm volatile("cp.async.cg.shared.global [%0], [%1], 16;\n" :: "r"(dst), "l"(src));
}
__device__ __forceinline__ void ldsm4(uint32_t* r, uint32_t addr) {
    asm volatile("ldmatrix.sync.aligned.m8n8.x4.shared.b16 {%0,%1,%2,%3}, [%4];\n"
                 : "=r"(r[0]), "=r"(r[1]), "=r"(r[2]), "=r"(r[3]) : "r"(addr));
}

__global__ void __launch_bounds__(256, 1)
gemm_kernel(const float* __restrict__ bias, float* __restrict__ out) {
    float* csw   = (float*)(smem + NSTG * STG);
    float* cbias = csw + GBN;

    const int tid = threadIdx.x, warp = tid >> 5, lane = tid & 31;
    const int wm = warp >> 2, wn = warp & 3;

    const int bid  = blockIdx.x;
    const int band = bid / (BAND * NT_N);
    const int rem  = bid % (BAND * NT_N);
    const int bn   = rem / BAND;
    const int bm   = band * BAND + rem % BAND;

    csw[tid]       = g_S * g_swf[bn * GBN + tid] * 0.0625f;
    csw[tid + 256] = 0.f;   // no-op filler avoided; (tid<256 always)
    cbias[tid]     = bias[bn * GBN + tid];

    const int8_t* Ag = g_aq + (size_t)(bm * GBM) * KK;
    const int8_t* Bg = g_bq + (size_t)(bn * GBN) * KK;
    const uint32_t sb = (uint32_t)__cvta_generic_to_shared(smem);

    int acc[4][8][4];
#pragma unroll
    for (int mt = 0; mt < 4; ++mt)
#pragma unroll
        for (int nt = 0; nt < 8; ++nt)
#pragma unroll
            for (int r = 0; r < 4; ++r) acc[mt][nt][r] = 0;

    auto load_tile = [&](int kt, int buf) {
        uint32_t so = sb + buf * STG;
#pragma unroll
        for (int h = 0; h < 2; ++h) {
            int id = tid + h * 256;
            int row = id >> 2, seg = id & 3;
            cp16(so + row * AST + seg * 16, Ag + (size_t)row * KK + kt * GBK + seg * 16);
        }
#pragma unroll
        for (int h = 0; h < 4; ++h) {
            int id = tid + h * 256;
            int row = id >> 2, seg = id & 3;
            cp16(so + ASTG + row * AST + seg * 16, Bg + (size_t)row * KK + kt * GBK + seg * 16);
        }
        asm volatile("cp.async.commit_group;\n");
    };

    auto compute = [&](int buf) {
        const uint32_t ab = sb + buf * STG;
        const uint32_t bb = ab + ASTG;
        const int li = (lane & 7) + ((lane >> 3) & 1) * 8;   // row-within-16
        const int hs = (lane >> 4);                          // 16B-half select
#pragma unroll
        for (int ks = 0; ks < 2; ++ks) {
            uint32_t a[4][4];
#pragma unroll
            for (int mt = 0; mt < 4; ++mt)
                ldsm4(a[mt], ab + (uint32_t)(wm * 64 + mt * 16 + li) * AST + (ks * 2 + hs) * 16);
            uint32_t b[8][2];
#pragma unroll
            for (int p = 0; p < 4; ++p) {
                uint32_t r[4];
                ldsm4(r, bb + (uint32_t)(wn * 64 + p * 16 + li) * AST + (ks * 2 + hs) * 16);
                b[2 * p][0] = r[0]; b[2 * p + 1][0] = r[1];
                b[2 * p][1] = r[2]; b[2 * p + 1][1] = r[3];
            }
#pragma unroll
            for (int mt = 0; mt < 4; ++mt) {
#pragma unroll
                for (int nt = 0; nt < 8; ++nt) {
                    asm volatile(
                        "mma.sync.aligned.m16n8k32.row.col.s32.s8.s8.s32 "
                        "{%0,%1,%2,%3}, {%4,%5,%6,%7}, {%8,%9}, {%0,%1,%2,%3};\n"
                        : "+r"(acc[mt][nt][0]), "+r"(acc[mt][nt][1]),
                          "+r"(acc[mt][nt][2]), "+r"(acc[mt][nt][3])
                        : "r"(a[mt][0]), "r"(a[mt][1]), "r"(a[mt][2]), "r"(a[mt][3]),
                          "r"(b[nt][0]), "r"(b[nt][1]));
                }
            }
        }
    };

    load_tile(0, 0);
    load_tile(1, 1);
    load_tile(2, 2);

    for (int kt = 0; kt < NCH; ++kt) {
        asm volatile("cp.async.wait_group 2;\n");
        __syncthreads();
        if (kt + 3 < NCH) load_tile(kt + 3, (kt + 3) & 3);
        compute(kt & 3);
    }

    // ---- epilogue: y = csw*acc + bias ----
#pragma unroll
    for (int nt = 0; nt < 8; ++nt) {
        int cl = wn * 64 + nt * 8 + (lane & 3) * 2;
        int c0 = bn * GBN + cl;
        float w0 = csw[cl], w1 = csw[cl + 1];
        float b0 = cbias[cl], b1 = cbias[cl + 1];
#pragma unroll
        for (int mt = 0; mt < 4; ++mt) {
            int r0 = bm * GBM + wm * 64 + mt * 16 + (lane >> 2);
            float2 v0 = make_float2((float)acc[mt][nt][0] * w0 + b0,
                                    (float)acc[mt][nt][1] * w1 + b1);
            float2 v1 = make_float2((float)acc[mt][nt][2] * w0 + b0,
                                    (float)acc[mt][nt][3] * w1 + b1);
            *reinterpret_cast<float2*>(out + (size_t)r0 * OUT_F + c0)       = v0;
            *reinterpret_cast<float2*>(out + (size_t)(r0 + 8) * OUT_F + c0) = v1;
        }
    }
}

// ============================================================================
// launch
// ============================================================================
extern "C" void kernel_launch(void* const* d_in, const int* in_sizes, int n_in,
                              void* d_out, int out_size) {
    const float* x    = (const float*)d_in[0];
    const void*  pw   = (const void*)d_in[1];
    const void*  s_w  = (const void*)d_in[2];
    const float* bias = (const float*)d_in[3];
    float*       out  = (float*)d_out;

    const int smem_bytes = NSTG * STG + 2 * GBN * 4 + 256;   // 124,928 B + slack
    static int smem_set = 0;
    if (!smem_set) {
        cudaFuncSetAttribute(gemm_kernel, cudaFuncAttributeMaxDynamicSharedMemorySize, smem_bytes);
        smem_set = 1;
    }

    detect_kernel<<<1, 1>>>(s_w, pw);
    quantile_kernel<<<IN_F / 64, 256>>>(x);
    smax_kernel<<<1, 256>>>();
    quant_x_kernel<<<(TOKENS * IN_F / 8) / 256, 256>>>(x);
    prep_w_kernel<<<(OUT_F * (IN_F / 2) / 4) / 256, 256>>>(pw);
    swf_kernel<<<OUT_F / 256, 256>>>(s_w);
    gemm_kernel<<<(TOKENS / GBM) * NT_N, 256, smem_bytes>>>(bias, out);
}

// round 9
// speedup vs baseline: 3.7822x; 3.7822x over previous
#include <cuda_runtime.h>
#include <cuda_fp16.h>
#include <stdint.h>

#define TOKENS 8192
#define IN_F   4096
#define OUT_F  11008

// ---------------- scratch (device globals; no allocation allowed) -----------
__device__ __align__(16) float  g_sa[IN_F];
__device__ __align__(16) __half g_xdeq[(size_t)TOKENS * IN_F];   // 64 MB
__device__ __align__(16) __half g_wdeq[(size_t)OUT_F  * IN_F];   // 88 MB (s_w folded in)
__device__ int g_sw_mode;     // 0 = f16, 1 = f32, 2 = bf16
__device__ int g_pw_is_i32;   // packed_w delivered as int32-per-byte

// ============================================================================
// Kernel 0: input dtype detection (harness upcasts f16 and uint8 inputs)
// ============================================================================
__global__ void detect_kernel(const void* __restrict__ s_w, const void* __restrict__ pw) {
    bool bf_ok = true;
    const uint16_t* u16 = (const uint16_t*)s_w;
#pragma unroll
    for (int i = 0; i < 16; ++i) {
        float v = __uint_as_float(((uint32_t)u16[i]) << 16);
        bf_ok = bf_ok && isfinite(v) && (v > 1e-4f) && (v < 0.5f);
    }
    bool f32_ok = true;
    const float* f = (const float*)s_w;
#pragma unroll
    for (int i = 0; i < 8; ++i) {
        float v = f[i];
        f32_ok = f32_ok && isfinite(v) && (v > 1e-4f) && (v < 0.5f);
    }
    g_sw_mode = bf_ok ? 2 : (f32_ok ? 1 : 0);

    const int* pi = (const int*)pw;
    bool i32_ok = true;
#pragma unroll
    for (int i = 0; i < 64; ++i) { int v = pi[i]; i32_ok = i32_ok && (v >= 0) && (v <= 255); }
    g_pw_is_i32 = i32_ok ? 1 : 0;
}

// ============================================================================
// Kernel 1: per-column 0.999 quantile of |x| -> s_a
// ============================================================================
__global__ void quantile_kernel(const float* __restrict__ x) {
    __shared__ float tops[256][10];
    const int t = threadIdx.x, cl = t & 63, chunk = t >> 6;
    const int col = blockIdx.x * 64 + cl;
    const float* p = x + (size_t)chunk * 2048 * IN_F + col;

    float tt[10];
#pragma unroll
    for (int i = 0; i < 10; ++i) tt[i] = -1.0f;
#pragma unroll 4
    for (int r = 0; r < 2048; ++r) {
        float v = fabsf(p[(size_t)r * IN_F]);
        if (v > tt[9]) {
            tt[9] = v;
#pragma unroll
            for (int j = 9; j > 0; --j)
                if (tt[j] > tt[j - 1]) { float tmp = tt[j - 1]; tt[j - 1] = tt[j]; tt[j] = tmp; }
        }
    }
#pragma unroll
    for (int i = 0; i < 10; ++i) tops[t][i] = tt[i];
    __syncthreads();

    if (chunk == 0) {
        int pi[4] = {0, 0, 0, 0};
        float v9th = 0.f, v10th = 0.f;
        for (int i = 0; i < 10; ++i) {
            int best = 0; float bv = tops[cl][pi[0]];
#pragma unroll
            for (int j = 1; j < 4; ++j) {
                float c = tops[cl + 64 * j][pi[j]];
                if (c > bv) { bv = c; best = j; }
            }
            pi[best]++;
            if (i == 8) v9th = bv;
            if (i == 9) v10th = bv;
        }
        float pos = 0.999f * 8191.0f;
        float qv  = v10th * (8183.0f - pos) + v9th * (pos - 8182.0f);
        float s = fmaxf(qv, 1e-6f) / 127.0f;
        s = fmaxf(s, 1e-6f);
        s = __half2float(__float2half_rn(s));
        g_sa[col] = s;
    }
}

// ============================================================================
// Kernel 2: fake-quant x -> fp16 x_deq (float4 per thread)
// ============================================================================
__global__ void quant_x_kernel(const float* __restrict__ x) {
    size_t i = (size_t)blockIdx.x * blockDim.x + threadIdx.x;
    float4 xv = reinterpret_cast<const float4*>(x)[i];
    float4 sv = reinterpret_cast<const float4*>(g_sa)[i & (IN_F / 4 - 1)];

    float q0 = fminf(fmaxf(rintf(xv.x / sv.x), -127.f), 127.f);
    float q1 = fminf(fmaxf(rintf(xv.y / sv.y), -127.f), 127.f);
    float q2 = fminf(fmaxf(rintf(xv.z / sv.z), -127.f), 127.f);
    float q3 = fminf(fmaxf(rintf(xv.w / sv.w), -127.f), 127.f);

    union { __half2 h2[2]; uint2 u; } pk;
    pk.h2[0] = __halves2half2(__float2half_rn(q0 * sv.x), __float2half_rn(q1 * sv.y));
    pk.h2[1] = __halves2half2(__float2half_rn(q2 * sv.z), __float2half_rn(q3 * sv.w));
    reinterpret_cast<uint2*>(g_xdeq)[i] = pk.u;
}

// ============================================================================
// Kernel 3: int4 unpack + scale -> fp16 w_deq (s_w folded in)
// ============================================================================
__global__ void dequant_w_kernel(const void* __restrict__ pw,
                                 const void* __restrict__ s_w) {
    size_t i = (size_t)blockIdx.x * blockDim.x + threadIdx.x;  // 4-byte group idx
    int b4[4];
    if (g_pw_is_i32) {
        int4 v = reinterpret_cast<const int4*>(pw)[i];
        b4[0] = v.x & 0xFF; b4[1] = v.y & 0xFF; b4[2] = v.z & 0xFF; b4[3] = v.w & 0xFF;
    } else {
        uint32_t w = reinterpret_cast<const uint32_t*>(pw)[i];
        b4[0] = w & 0xFF; b4[1] = (w >> 8) & 0xFF; b4[2] = (w >> 16) & 0xFF; b4[3] = (w >> 24) & 0xFF;
    }
    int o = (int)(i >> 9);
    float sw;
    int mode = g_sw_mode;
    if (mode == 1)      sw = ((const float*)s_w)[o];
    else if (mode == 2) sw = __uint_as_float(((uint32_t)((const uint16_t*)s_w)[o]) << 16);
    else                sw = __half2float(((const __half*)s_w)[o]);

    union { __half2 h2[4]; uint4 u; } pk;
#pragma unroll
    for (int j = 0; j < 4; ++j) {
        int b  = b4[j];
        int lo = b & 15;  lo = (lo >= 8) ? lo - 16 : lo;
        int hi = b >> 4;  hi = (hi >= 8) ? hi - 16 : hi;
        pk.h2[j] = __halves2half2(__float2half_rn((float)lo * sw),
                                  __float2half_rn((float)hi * sw));
    }
    reinterpret_cast<uint4*>(g_wdeq)[i] = pk.u;
}

// ============================================================================
// Kernel 4: GEMM  out[8192,11008] = x_deq @ w_deq^T + bias
//   CTA 128x128x32, 256 threads (2x4 warps, warp 64x32), 3-stage cp.async,
//   ldmatrix + mma.m16n8k16 with F16 ACCUMULATORS, flushed to f32 every K=64
//   (4 mmas) to bound rounding error while (potentially) running at the
//   double-rate f16-acc HMMA issue rate.
// ============================================================================
#define GBM 128
#define GBN 128
#define GBK 32
#define GST 40      // smem row stride in halves (32 + 8 pad)
#define NSTG 3
#define ASTG (GBM * GST)
#define BSTG (GBN * GST)
#define NCH  (IN_F / GBK)            // 128

extern __shared__ __align__(16) __half g_smem[];

__global__ void __launch_bounds__(256)
gemm_kernel(const float* __restrict__ bias, float* __restrict__ out) {
    __half* As = g_smem;                 // NSTG * ASTG
    __half* Bs = g_smem + NSTG * ASTG;   // NSTG * BSTG

    const int tid  = threadIdx.x;
    const int warp = tid >> 5, lane = tid & 31;
    const int wm = warp >> 2, wn = warp & 3;
    const int bn = blockIdx.x, bm = blockIdx.y;

    const __half* Ag = g_xdeq + (size_t)(bm * GBM) * IN_F;
    const __half* Bg = g_wdeq + (size_t)(bn * GBN) * IN_F;

    const uint32_t as_base = (uint32_t)__cvta_generic_to_shared(As);
    const uint32_t bs_base = (uint32_t)__cvta_generic_to_shared(Bs);

    float    facc[4][4][4];              // fp32 master accumulators
    uint32_t hacc[4][4][2];              // f16x2 segment accumulators
#pragma unroll
    for (int mt = 0; mt < 4; ++mt)
#pragma unroll
        for (int nt = 0; nt < 4; ++nt) {
#pragma unroll
            for (int r = 0; r < 4; ++r) facc[mt][nt][r] = 0.f;
            hacc[mt][nt][0] = 0u; hacc[mt][nt][1] = 0u;
        }

    auto load_tile = [&](int kt, int buf) {
#pragma unroll
        for (int h = 0; h < 2; ++h) {
            int c    = tid + h * 256;
            int row  = c >> 2;
            int col8 = (c & 3) * 8;
            const __half* ga = Ag + (size_t)row * IN_F + kt * GBK + col8;
            uint32_t sa = as_base + (uint32_t)(buf * ASTG + row * GST + col8) * 2u;
            asm volatile("cp.async.cg.shared.global [%0], [%1], 16;\n" :: "r"(sa), "l"(ga));
            const __half* gb = Bg + (size_t)row * IN_F + kt * GBK + col8;
            uint32_t sb = bs_base + (uint32_t)(buf * BSTG + row * GST + col8) * 2u;
            asm volatile("cp.async.cg.shared.global [%0], [%1], 16;\n" :: "r"(sb), "l"(gb));
        }
        asm volatile("cp.async.commit_group;\n");
    };

    auto compute = [&](int buf) {
        const int g   = lane >> 3;
        const int idx = lane & 7;
#pragma unroll
        for (int kk = 0; kk < GBK; kk += 16) {
            uint32_t a[4][4];
#pragma unroll
            for (int mt = 0; mt < 4; ++mt) {
                int row = wm * 64 + mt * 16 + idx + (g & 1) * 8;
                int col = kk + (g >> 1) * 8;
                uint32_t addr = as_base + (uint32_t)(buf * ASTG + row * GST + col) * 2u;
                asm volatile("ldmatrix.sync.aligned.m8n8.x4.shared.b16 {%0,%1,%2,%3}, [%4];\n"
                             : "=r"(a[mt][0]), "=r"(a[mt][1]), "=r"(a[mt][2]), "=r"(a[mt][3])
                             : "r"(addr));
            }
            uint32_t b[2][4];
#pragma unroll
            for (int bt = 0; bt < 2; ++bt) {
                int n   = wn * 32 + bt * 16 + idx + (g >> 1) * 8;
                int col = kk + (g & 1) * 8;
                uint32_t addr = bs_base + (uint32_t)(buf * BSTG + n * GST + col) * 2u;
                asm volatile("ldmatrix.sync.aligned.m8n8.x4.shared.b16 {%0,%1,%2,%3}, [%4];\n"
                             : "=r"(b[bt][0]), "=r"(b[bt][1]), "=r"(b[bt][2]), "=r"(b[bt][3])
                             : "r"(addr));
            }
#pragma unroll
            for (int mt = 0; mt < 4; ++mt) {
#pragma unroll
                for (int nt = 0; nt < 4; ++nt) {
                    uint32_t b0 = b[nt >> 1][(nt & 1) * 2];
                    uint32_t b1 = b[nt >> 1][(nt & 1) * 2 + 1];
                    asm volatile(
                        "mma.sync.aligned.m16n8k16.row.col.f16.f16.f16.f16 "
                        "{%0,%1}, {%2,%3,%4,%5}, {%6,%7}, {%0,%1};\n"
                        : "+r"(hacc[mt][nt][0]), "+r"(hacc[mt][nt][1])
                        : "r"(a[mt][0]), "r"(a[mt][1]), "r"(a[mt][2]), "r"(a[mt][3]),
                          "r"(b0), "r"(b1));
                }
            }
        }
    };

    auto flush = [&]() {
#pragma unroll
        for (int mt = 0; mt < 4; ++mt)
#pragma unroll
            for (int nt = 0; nt < 4; ++nt) {
                float2 lo = __half22float2(*reinterpret_cast<__half2*>(&hacc[mt][nt][0]));
                float2 hi = __half22float2(*reinterpret_cast<__half2*>(&hacc[mt][nt][1]));
                facc[mt][nt][0] += lo.x;  facc[mt][nt][1] += lo.y;
                facc[mt][nt][2] += hi.x;  facc[mt][nt][3] += hi.y;
                hacc[mt][nt][0] = 0u;     hacc[mt][nt][1] = 0u;
            }
    };

    // ---- 3-stage pipelined main loop; flush f16 partials every 2 chunks ----
    load_tile(0, 0);
    load_tile(1, 1);

    for (int kt = 0; kt < NCH; ++kt) {
        asm volatile("cp.async.wait_group 1;\n");
        __syncthreads();
        if (kt + 2 < NCH) load_tile(kt + 2, (kt + 2) % NSTG);
        compute(kt % NSTG);
        if (kt & 1) flush();
    }

    // ---- epilogue: + bias, fp32 store ----
#pragma unroll
    for (int nt = 0; nt < 4; ++nt) {
        int c0 = bn * GBN + wn * 32 + nt * 8 + (lane & 3) * 2;
        float b0 = bias[c0], b1 = bias[c0 + 1];
#pragma unroll
        for (int mt = 0; mt < 4; ++mt) {
            int r0 = bm * GBM + wm * 64 + mt * 16 + (lane >> 2);
            float2 v0 = make_float2(facc[mt][nt][0] + b0, facc[mt][nt][1] + b1);
            float2 v1 = make_float2(facc[mt][nt][2] + b0, facc[mt][nt][3] + b1);
            *reinterpret_cast<float2*>(out + (size_t)r0 * OUT_F + c0)       = v0;
            *reinterpret_cast<float2*>(out + (size_t)(r0 + 8) * OUT_F + c0) = v1;
        }
    }
}

// ============================================================================
// launch
// ============================================================================
extern "C" void kernel_launch(void* const* d_in, const int* in_sizes, int n_in,
                              void* d_out, int out_size) {
    const float* x    = (const float*)d_in[0];
    const void*  pw   = (const void*)d_in[1];
    const void*  s_w  = (const void*)d_in[2];
    const float* bias = (const float*)d_in[3];
    float*       out  = (float*)d_out;

    const int smem_bytes = NSTG * (ASTG + BSTG) * 2;   // 61,440 B
    static int smem_set = 0;
    if (!smem_set) {
        cudaFuncSetAttribute(gemm_kernel, cudaFuncAttributeMaxDynamicSharedMemorySize, smem_bytes);
        smem_set = 1;
    }

    detect_kernel<<<1, 1>>>(s_w, pw);
    quantile_kernel<<<IN_F / 64, 256>>>(x);
    quant_x_kernel<<<(TOKENS * IN_F / 4) / 256, 256>>>(x);
    dequant_w_kernel<<<(OUT_F * (IN_F / 2) / 4) / 256, 256>>>(pw, s_w);
    gemm_kernel<<<dim3(OUT_F / GBN, TOKENS / GBM), 256, smem_bytes>>>(bias, out);
}

// round 10
// speedup vs baseline: 3.9365x; 1.0408x over previous
#include <cuda_runtime.h>
#include <cuda_fp16.h>
#include <stdint.h>

#define TOKENS 8192
#define IN_F   4096
#define OUT_F  11008

// ---------------- scratch (device globals; no allocation allowed) -----------
__device__ __align__(16) float  g_sa[IN_F];
__device__ __align__(16) float  g_rsa[IN_F];                     // 1 / s_a
__device__ __align__(16) __half g_xdeq[(size_t)TOKENS * IN_F];   // 64 MB
__device__ __align__(16) __half g_wdeq[(size_t)OUT_F  * IN_F];   // 88 MB (s_w folded in)
__device__ int g_sw_mode;     // 0 = f16, 1 = f32, 2 = bf16
__device__ int g_pw_is_i32;   // packed_w delivered as int32-per-byte

// ============================================================================
// Kernel 0: input dtype detection (harness upcasts f16 and uint8 inputs)
// ============================================================================
__global__ void detect_kernel(const void* __restrict__ s_w, const void* __restrict__ pw) {
    bool bf_ok = true;
    const uint16_t* u16 = (const uint16_t*)s_w;
#pragma unroll
    for (int i = 0; i < 16; ++i) {
        float v = __uint_as_float(((uint32_t)u16[i]) << 16);
        bf_ok = bf_ok && isfinite(v) && (v > 1e-4f) && (v < 0.5f);
    }
    bool f32_ok = true;
    const float* f = (const float*)s_w;
#pragma unroll
    for (int i = 0; i < 8; ++i) {
        float v = f[i];
        f32_ok = f32_ok && isfinite(v) && (v > 1e-4f) && (v < 0.5f);
    }
    g_sw_mode = bf_ok ? 2 : (f32_ok ? 1 : 0);

    const int* pi = (const int*)pw;
    bool i32_ok = true;
#pragma unroll
    for (int i = 0; i < 64; ++i) { int v = pi[i]; i32_ok = i32_ok && (v >= 0) && (v <= 255); }
    g_pw_is_i32 = i32_ok ? 1 : 0;
}

// ============================================================================
// Kernel 1: per-column 0.999 quantile of |x| -> s_a (and 1/s_a)
// ============================================================================
__global__ void quantile_kernel(const float* __restrict__ x) {
    __shared__ float tops[256][10];
    const int t = threadIdx.x, cl = t & 63, chunk = t >> 6;
    const int col = blockIdx.x * 64 + cl;
    const float* p = x + (size_t)chunk * 2048 * IN_F + col;

    float tt[10];
#pragma unroll
    for (int i = 0; i < 10; ++i) tt[i] = -1.0f;
#pragma unroll 4
    for (int r = 0; r < 2048; ++r) {
        float v = fabsf(p[(size_t)r * IN_F]);
        if (v > tt[9]) {
            tt[9] = v;
#pragma unroll
            for (int j = 9; j > 0; --j)
                if (tt[j] > tt[j - 1]) { float tmp = tt[j - 1]; tt[j - 1] = tt[j]; tt[j] = tmp; }
        }
    }
#pragma unroll
    for (int i = 0; i < 10; ++i) tops[t][i] = tt[i];
    __syncthreads();

    if (chunk == 0) {
        int pi[4] = {0, 0, 0, 0};
        float v9th = 0.f, v10th = 0.f;
        for (int i = 0; i < 10; ++i) {
            int best = 0; float bv = tops[cl][pi[0]];
#pragma unroll
            for (int j = 1; j < 4; ++j) {
                float c = tops[cl + 64 * j][pi[j]];
                if (c > bv) { bv = c; best = j; }
            }
            pi[best]++;
            if (i == 8) v9th = bv;
            if (i == 9) v10th = bv;
        }
        float pos = 0.999f * 8191.0f;
        float qv  = v10th * (8183.0f - pos) + v9th * (pos - 8182.0f);
        float s = fmaxf(qv, 1e-6f) / 127.0f;
        s = fmaxf(s, 1e-6f);
        s = __half2float(__float2half_rn(s));
        g_sa[col]  = s;
        g_rsa[col] = 1.0f / s;
    }
}

// ============================================================================
// Kernel 2: fake-quant x -> fp16 x_deq. 8 elements/thread, reciprocal multiply.
// ============================================================================
__global__ void quant_x_kernel(const float* __restrict__ x) {
    size_t i = (size_t)blockIdx.x * blockDim.x + threadIdx.x;   // 8-elem group
    size_t base = i * 8;
    int kb = (int)(base & (IN_F - 1));

    const float4* xp = (const float4*)(x + base);
    float4 x0 = xp[0], x1 = xp[1];
    const float4* sp = (const float4*)(g_sa + kb);
    float4 s0 = sp[0], s1 = sp[1];
    const float4* rp = (const float4*)(g_rsa + kb);
    float4 r0 = rp[0], r1 = rp[1];

    float xs[8] = {x0.x, x0.y, x0.z, x0.w, x1.x, x1.y, x1.z, x1.w};
    float ss[8] = {s0.x, s0.y, s0.z, s0.w, s1.x, s1.y, s1.z, s1.w};
    float rs[8] = {r0.x, r0.y, r0.z, r0.w, r1.x, r1.y, r1.z, r1.w};

    union { __half2 h2[4]; uint4 u; } pk;
#pragma unroll
    for (int j = 0; j < 8; j += 2) {
        float q0 = fminf(fmaxf(rintf(xs[j]     * rs[j]),     -127.f), 127.f);
        float q1 = fminf(fmaxf(rintf(xs[j + 1] * rs[j + 1]), -127.f), 127.f);
        pk.h2[j >> 1] = __halves2half2(__float2half_rn(q0 * ss[j]),
                                       __float2half_rn(q1 * ss[j + 1]));
    }
    reinterpret_cast<uint4*>(g_xdeq)[i] = pk.u;
}

// ============================================================================
// Kernel 3: int4 unpack + scale -> fp16 w_deq (s_w folded in).
// 8 packed bytes/thread -> 16 halves (2 x uint4).
// ============================================================================
__global__ void dequant_w_kernel(const void* __restrict__ pw,
                                 const void* __restrict__ s_w) {
    size_t i = (size_t)blockIdx.x * blockDim.x + threadIdx.x;  // 8-byte group idx
    int b8[8];
    if (g_pw_is_i32) {
        const int4* p = (const int4*)pw + i * 2;
        int4 a = p[0], b = p[1];
        b8[0] = a.x & 0xFF; b8[1] = a.y & 0xFF; b8[2] = a.z & 0xFF; b8[3] = a.w & 0xFF;
        b8[4] = b.x & 0xFF; b8[5] = b.y & 0xFF; b8[6] = b.z & 0xFF; b8[7] = b.w & 0xFF;
    } else {
        uint2 w = reinterpret_cast<const uint2*>(pw)[i];
#pragma unroll
        for (int j = 0; j < 4; ++j) { b8[j] = (w.x >> (8 * j)) & 0xFF; b8[4 + j] = (w.y >> (8 * j)) & 0xFF; }
    }
    int o = (int)(i >> 8);                       // 256 groups per output row
    float sw;
    int mode = g_sw_mode;
    if (mode == 1)      sw = ((const float*)s_w)[o];
    else if (mode == 2) sw = __uint_as_float(((uint32_t)((const uint16_t*)s_w)[o]) << 16);
    else                sw = __half2float(((const __half*)s_w)[o]);

    union { __half2 h2[8]; uint4 u[2]; } pk;
#pragma unroll
    for (int j = 0; j < 8; ++j) {
        int b  = b8[j];
        int lo = ((b & 15) ^ 8) - 8;
        int hi = ((b >> 4) ^ 8) - 8;
        pk.h2[j] = __halves2half2(__float2half_rn((float)lo * sw),
                                  __float2half_rn((float)hi * sw));
    }
    uint4* dst = reinterpret_cast<uint4*>(g_wdeq) + i * 2;
    dst[0] = pk.u[0];
    dst[1] = pk.u[1];
}

// ============================================================================
// Kernel 4: GEMM  out[8192,11008] = x_deq @ w_deq^T + bias
//   CTA 128x128x32, 256 threads (2x4 warps, warp 64x32), 3-stage cp.async
//   (wait_group 1), ldmatrix + mma.m16n8k16 f32acc.  (Legacy HMMA rt=16
//   ceiling: this configuration measured at 99% of it in R3.)
// ============================================================================
#define GBM 128
#define GBN 128
#define GBK 32
#define GST 40      // smem row stride in halves (32 + 8 pad)
#define NSTG 3
#define ASTG (GBM * GST)
#define BSTG (GBN * GST)
#define NCH  (IN_F / GBK)            // 128

extern __shared__ __align__(16) __half g_smem[];

__global__ void __launch_bounds__(256)
gemm_kernel(const float* __restrict__ bias, float* __restrict__ out) {
    __half* As = g_smem;                 // NSTG * ASTG
    __half* Bs = g_smem + NSTG * ASTG;   // NSTG * BSTG

    const int tid  = threadIdx.x;
    const int warp = tid >> 5, lane = tid & 31;
    const int wm = warp >> 2, wn = warp & 3;
    const int bn = blockIdx.x, bm = blockIdx.y;

    const __half* Ag = g_xdeq + (size_t)(bm * GBM) * IN_F;
    const __half* Bg = g_wdeq + (size_t)(bn * GBN) * IN_F;

    const uint32_t as_base = (uint32_t)__cvta_generic_to_shared(As);
    const uint32_t bs_base = (uint32_t)__cvta_generic_to_shared(Bs);

    float acc[4][4][4];
#pragma unroll
    for (int mt = 0; mt < 4; ++mt)
#pragma unroll
        for (int nt = 0; nt < 4; ++nt)
#pragma unroll
            for (int r = 0; r < 4; ++r) acc[mt][nt][r] = 0.f;

    auto load_tile = [&](int kt, int buf) {
#pragma unroll
        for (int h = 0; h < 2; ++h) {
            int c    = tid + h * 256;
            int row  = c >> 2;
            int col8 = (c & 3) * 8;
            const __half* ga = Ag + (size_t)row * IN_F + kt * GBK + col8;
            uint32_t sa = as_base + (uint32_t)(buf * ASTG + row * GST + col8) * 2u;
            asm volatile("cp.async.cg.shared.global [%0], [%1], 16;\n" :: "r"(sa), "l"(ga));
            const __half* gb = Bg + (size_t)row * IN_F + kt * GBK + col8;
            uint32_t sb = bs_base + (uint32_t)(buf * BSTG + row * GST + col8) * 2u;
            asm volatile("cp.async.cg.shared.global [%0], [%1], 16;\n" :: "r"(sb), "l"(gb));
        }
        asm volatile("cp.async.commit_group;\n");
    };

    auto compute = [&](int buf) {
        const int g   = lane >> 3;
        const int idx = lane & 7;
#pragma unroll
        for (int kk = 0; kk < GBK; kk += 16) {
            uint32_t a[4][4];
#pragma unroll
            for (int mt = 0; mt < 4; ++mt) {
                int row = wm * 64 + mt * 16 + idx + (g & 1) * 8;
                int col = kk + (g >> 1) * 8;
                uint32_t addr = as_base + (uint32_t)(buf * ASTG + row * GST + col) * 2u;
                asm volatile("ldmatrix.sync.aligned.m8n8.x4.shared.b16 {%0,%1,%2,%3}, [%4];\n"
                             : "=r"(a[mt][0]), "=r"(a[mt][1]), "=r"(a[mt][2]), "=r"(a[mt][3])
                             : "r"(addr));
            }
            uint32_t b[2][4];
#pragma unroll
            for (int bt = 0; bt < 2; ++bt) {
                int n   = wn * 32 + bt * 16 + idx + (g >> 1) * 8;
                int col = kk + (g & 1) * 8;
                uint32_t addr = bs_base + (uint32_t)(buf * BSTG + n * GST + col) * 2u;
                asm volatile("ldmatrix.sync.aligned.m8n8.x4.shared.b16 {%0,%1,%2,%3}, [%4];\n"
                             : "=r"(b[bt][0]), "=r"(b[bt][1]), "=r"(b[bt][2]), "=r"(b[bt][3])
                             : "r"(addr));
            }
#pragma unroll
            for (int mt = 0; mt < 4; ++mt) {
#pragma unroll
                for (int nt = 0; nt < 4; ++nt) {
                    uint32_t b0 = b[nt >> 1][(nt & 1) * 2];
                    uint32_t b1 = b[nt >> 1][(nt & 1) * 2 + 1];
                    asm volatile(
                        "mma.sync.aligned.m16n8k16.row.col.f32.f16.f16.f32 "
                        "{%0,%1,%2,%3}, {%4,%5,%6,%7}, {%8,%9}, {%0,%1,%2,%3};\n"
                        : "+f"(acc[mt][nt][0]), "+f"(acc[mt][nt][1]),
                          "+f"(acc[mt][nt][2]), "+f"(acc[mt][nt][3])
                        : "r"(a[mt][0]), "r"(a[mt][1]), "r"(a[mt][2]), "r"(a[mt][3]),
                          "r"(b0), "r"(b1));
                }
            }
        }
    };

    // ---- 3-stage pipelined main loop ----
    load_tile(0, 0);
    load_tile(1, 1);

    for (int kt = 0; kt < NCH; ++kt) {
        asm volatile("cp.async.wait_group 1;\n");
        __syncthreads();
        if (kt + 2 < NCH) load_tile(kt + 2, (kt + 2) % NSTG);
        compute(kt % NSTG);
    }

    // ---- epilogue: + bias, fp32 store ----
#pragma unroll
    for (int nt = 0; nt < 4; ++nt) {
        int c0 = bn * GBN + wn * 32 + nt * 8 + (lane & 3) * 2;
        float b0 = bias[c0], b1 = bias[c0 + 1];
#pragma unroll
        for (int mt = 0; mt < 4; ++mt) {
            int r0 = bm * GBM + wm * 64 + mt * 16 + (lane >> 2);
            float2 v0 = make_float2(acc[mt][nt][0] + b0, acc[mt][nt][1] + b1);
            float2 v1 = make_float2(acc[mt][nt][2] + b0, acc[mt][nt][3] + b1);
            *reinterpret_cast<float2*>(out + (size_t)r0 * OUT_F + c0)       = v0;
            *reinterpret_cast<float2*>(out + (size_t)(r0 + 8) * OUT_F + c0) = v1;
        }
    }
}

// ============================================================================
// launch
// ============================================================================
extern "C" void kernel_launch(void* const* d_in, const int* in_sizes, int n_in,
                              void* d_out, int out_size) {
    const float* x    = (const float*)d_in[0];
    const void*  pw   = (const void*)d_in[1];
    const void*  s_w  = (const void*)d_in[2];
    const float* bias = (const float*)d_in[3];
    float*       out  = (float*)d_out;

    const int smem_bytes = NSTG * (ASTG + BSTG) * 2;   // 61,440 B
    static int smem_set = 0;
    if (!smem_set) {
        cudaFuncSetAttribute(gemm_kernel, cudaFuncAttributeMaxDynamicSharedMemorySize, smem_bytes);
        smem_set = 1;
    }

    detect_kernel<<<1, 1>>>(s_w, pw);
    quantile_kernel<<<IN_F / 64, 256>>>(x);
    quant_x_kernel<<<(TOKENS * IN_F / 8) / 256, 256>>>(x);
    dequant_w_kernel<<<(OUT_F * (IN_F / 2) / 8) / 256, 256>>>(pw, s_w);
    gemm_kernel<<<dim3(OUT_F / GBN, TOKENS / GBM), 256, smem_bytes>>>(bias, out);
}

// round 11
// speedup vs baseline: 4.0132x; 1.0195x over previous
#include <cuda_runtime.h>
#include <cuda_fp16.h>
#include <stdint.h>

#define TOKENS 8192
#define IN_F   4096
#define OUT_F  11008

// ---------------- scratch (device globals; no allocation allowed) -----------
__device__ __align__(16) float  g_sa[IN_F];
__device__ __align__(16) float  g_rsa[IN_F];                     // 1 / s_a
__device__ __align__(16) __half g_xdeq[(size_t)TOKENS * IN_F];   // 64 MB
__device__ __align__(16) __half g_wdeq[(size_t)OUT_F  * IN_F];   // 88 MB (s_w folded in)
__device__ int g_sw_mode;     // 0 = f16, 1 = f32, 2 = bf16
__device__ int g_pw_is_i32;   // packed_w delivered as int32-per-byte

// ============================================================================
// Kernel 0: input dtype detection (harness upcasts f16 and uint8 inputs)
// ============================================================================
__global__ void detect_kernel(const void* __restrict__ s_w, const void* __restrict__ pw) {
    bool bf_ok = true;
    const uint16_t* u16 = (const uint16_t*)s_w;
#pragma unroll
    for (int i = 0; i < 16; ++i) {
        float v = __uint_as_float(((uint32_t)u16[i]) << 16);
        bf_ok = bf_ok && isfinite(v) && (v > 1e-4f) && (v < 0.5f);
    }
    bool f32_ok = true;
    const float* f = (const float*)s_w;
#pragma unroll
    for (int i = 0; i < 8; ++i) {
        float v = f[i];
        f32_ok = f32_ok && isfinite(v) && (v > 1e-4f) && (v < 0.5f);
    }
    g_sw_mode = bf_ok ? 2 : (f32_ok ? 1 : 0);

    const int* pi = (const int*)pw;
    bool i32_ok = true;
#pragma unroll
    for (int i = 0; i < 64; ++i) { int v = pi[i]; i32_ok = i32_ok && (v >= 0) && (v <= 255); }
    g_pw_is_i32 = i32_ok ? 1 : 0;
}

// ============================================================================
// Kernel 1: per-column 0.999 quantile of |x| -> s_a (and 1/s_a)
// ============================================================================
__global__ void quantile_kernel(const float* __restrict__ x) {
    __shared__ float tops[256][10];
    const int t = threadIdx.x, cl = t & 63, chunk = t >> 6;
    const int col = blockIdx.x * 64 + cl;
    const float* p = x + (size_t)chunk * 2048 * IN_F + col;

    float tt[10];
#pragma unroll
    for (int i = 0; i < 10; ++i) tt[i] = -1.0f;
#pragma unroll 4
    for (int r = 0; r < 2048; ++r) {
        float v = fabsf(p[(size_t)r * IN_F]);
        if (v > tt[9]) {
            tt[9] = v;
#pragma unroll
            for (int j = 9; j > 0; --j)
                if (tt[j] > tt[j - 1]) { float tmp = tt[j - 1]; tt[j - 1] = tt[j]; tt[j] = tmp; }
        }
    }
#pragma unroll
    for (int i = 0; i < 10; ++i) tops[t][i] = tt[i];
    __syncthreads();

    if (chunk == 0) {
        int pi[4] = {0, 0, 0, 0};
        float v9th = 0.f, v10th = 0.f;
        for (int i = 0; i < 10; ++i) {
            int best = 0; float bv = tops[cl][pi[0]];
#pragma unroll
            for (int j = 1; j < 4; ++j) {
                float c = tops[cl + 64 * j][pi[j]];
                if (c > bv) { bv = c; best = j; }
            }
            pi[best]++;
            if (i == 8) v9th = bv;
            if (i == 9) v10th = bv;
        }
        float pos = 0.999f * 8191.0f;
        float qv  = v10th * (8183.0f - pos) + v9th * (pos - 8182.0f);
        float s = fmaxf(qv, 1e-6f) / 127.0f;
        s = fmaxf(s, 1e-6f);
        s = __half2float(__float2half_rn(s));
        g_sa[col]  = s;
        g_rsa[col] = 1.0f / s;
    }
}

// ============================================================================
// Kernel 2: fake-quant x -> fp16 x_deq. 8 elements/thread, reciprocal multiply.
// ============================================================================
__global__ void quant_x_kernel(const float* __restrict__ x) {
    size_t i = (size_t)blockIdx.x * blockDim.x + threadIdx.x;   // 8-elem group
    size_t base = i * 8;
    int kb = (int)(base & (IN_F - 1));

    const float4* xp = (const float4*)(x + base);
    float4 x0 = xp[0], x1 = xp[1];
    const float4* sp = (const float4*)(g_sa + kb);
    float4 s0 = sp[0], s1 = sp[1];
    const float4* rp = (const float4*)(g_rsa + kb);
    float4 r0 = rp[0], r1 = rp[1];

    float xs[8] = {x0.x, x0.y, x0.z, x0.w, x1.x, x1.y, x1.z, x1.w};
    float ss[8] = {s0.x, s0.y, s0.z, s0.w, s1.x, s1.y, s1.z, s1.w};
    float rs[8] = {r0.x, r0.y, r0.z, r0.w, r1.x, r1.y, r1.z, r1.w};

    union { __half2 h2[4]; uint4 u; } pk;
#pragma unroll
    for (int j = 0; j < 8; j += 2) {
        float q0 = fminf(fmaxf(rintf(xs[j]     * rs[j]),     -127.f), 127.f);
        float q1 = fminf(fmaxf(rintf(xs[j + 1] * rs[j + 1]), -127.f), 127.f);
        pk.h2[j >> 1] = __halves2half2(__float2half_rn(q0 * ss[j]),
                                       __float2half_rn(q1 * ss[j + 1]));
    }
    reinterpret_cast<uint4*>(g_xdeq)[i] = pk.u;
}

// ============================================================================
// Kernel 3: int4 unpack + scale -> fp16 w_deq (s_w folded in).
// 8 packed bytes/thread -> 16 halves (2 x uint4).
// ============================================================================
__global__ void dequant_w_kernel(const void* __restrict__ pw,
                                 const void* __restrict__ s_w) {
    size_t i = (size_t)blockIdx.x * blockDim.x + threadIdx.x;  // 8-byte group idx
    int b8[8];
    if (g_pw_is_i32) {
        const int4* p = (const int4*)pw + i * 2;
        int4 a = p[0], b = p[1];
        b8[0] = a.x & 0xFF; b8[1] = a.y & 0xFF; b8[2] = a.z & 0xFF; b8[3] = a.w & 0xFF;
        b8[4] = b.x & 0xFF; b8[5] = b.y & 0xFF; b8[6] = b.z & 0xFF; b8[7] = b.w & 0xFF;
    } else {
        uint2 w = reinterpret_cast<const uint2*>(pw)[i];
#pragma unroll
        for (int j = 0; j < 4; ++j) { b8[j] = (w.x >> (8 * j)) & 0xFF; b8[4 + j] = (w.y >> (8 * j)) & 0xFF; }
    }
    int o = (int)(i >> 8);                       // 256 groups per output row
    float sw;
    int mode = g_sw_mode;
    if (mode == 1)      sw = ((const float*)s_w)[o];
    else if (mode == 2) sw = __uint_as_float(((uint32_t)((const uint16_t*)s_w)[o]) << 16);
    else                sw = __half2float(((const __half*)s_w)[o]);

    union { __half2 h2[8]; uint4 u[2]; } pk;
#pragma unroll
    for (int j = 0; j < 8; ++j) {
        int b  = b8[j];
        int lo = ((b & 15) ^ 8) - 8;
        int hi = ((b >> 4) ^ 8) - 8;
        pk.h2[j] = __halves2half2(__float2half_rn((float)lo * sw),
                                  __float2half_rn((float)hi * sw));
    }
    uint4* dst = reinterpret_cast<uint4*>(g_wdeq) + i * 2;
    dst[0] = pk.u[0];
    dst[1] = pk.u[1];
}

// ============================================================================
// Kernel 4: GEMM  out[8192,11008] = x_deq @ w_deq^T + bias
//   EXACT round-3 structure (measured 99% of legacy-HMMA rt=16 ceiling):
//   CTA 128x128x32, 256 threads (2x4 warps, warp 64x32), 2-stage double
//   buffer, wait AFTER compute, one __syncthreads per chunk.
// ============================================================================
#define GBM 128
#define GBN 128
#define GBK 32
#define GST 40      // smem row stride in halves (32 + 8 pad -> ldmatrix conflict-free)

__global__ void __launch_bounds__(256)
gemm_kernel(const float* __restrict__ bias, float* __restrict__ out) {
    __shared__ __align__(16) __half As[2][GBM * GST];
    __shared__ __align__(16) __half Bs[2][GBN * GST];

    const int bn = blockIdx.x, bm = blockIdx.y;
    const int tid  = threadIdx.x;
    const int warp = tid >> 5, lane = tid & 31;
    const int wm = warp >> 2, wn = warp & 3;

    const __half* Ag = g_xdeq + (size_t)(bm * GBM) * IN_F;
    const __half* Bg = g_wdeq + (size_t)(bn * GBN) * IN_F;

    const uint32_t as_base = (uint32_t)__cvta_generic_to_shared(&As[0][0]);
    const uint32_t bs_base = (uint32_t)__cvta_generic_to_shared(&Bs[0][0]);

    float acc[4][4][4];
#pragma unroll
    for (int mt = 0; mt < 4; ++mt)
#pragma unroll
        for (int nt = 0; nt < 4; ++nt)
#pragma unroll
            for (int r = 0; r < 4; ++r) acc[mt][nt][r] = 0.f;

    auto load_tile = [&](int kt, int buf) {
#pragma unroll
        for (int h = 0; h < 2; ++h) {
            int c    = tid + h * 256;
            int row  = c >> 2;
            int col8 = (c & 3) * 8;
            const __half* ga = Ag + (size_t)row * IN_F + kt * GBK + col8;
            uint32_t sa = as_base + (uint32_t)(buf * GBM * GST + row * GST + col8) * 2u;
            asm volatile("cp.async.cg.shared.global [%0], [%1], 16;\n" :: "r"(sa), "l"(ga));
            const __half* gb = Bg + (size_t)row * IN_F + kt * GBK + col8;
            uint32_t sb = bs_base + (uint32_t)(buf * GBN * GST + row * GST + col8) * 2u;
            asm volatile("cp.async.cg.shared.global [%0], [%1], 16;\n" :: "r"(sb), "l"(gb));
        }
    };

    auto compute = [&](int buf) {
        const int g   = lane >> 3;
        const int idx = lane & 7;
#pragma unroll
        for (int kk = 0; kk < GBK; kk += 16) {
            uint32_t a[4][4];
#pragma unroll
            for (int mt = 0; mt < 4; ++mt) {
                int row = wm * 64 + mt * 16 + idx + (g & 1) * 8;
                int col = kk + (g >> 1) * 8;
                uint32_t addr = as_base + (uint32_t)(buf * GBM * GST + row * GST + col) * 2u;
                asm volatile("ldmatrix.sync.aligned.m8n8.x4.shared.b16 {%0,%1,%2,%3}, [%4];\n"
                             : "=r"(a[mt][0]), "=r"(a[mt][1]), "=r"(a[mt][2]), "=r"(a[mt][3])
                             : "r"(addr));
            }
            uint32_t b[2][4];
#pragma unroll
            for (int bt = 0; bt < 2; ++bt) {
                int n   = wn * 32 + bt * 16 + idx + (g >> 1) * 8;
                int col = kk + (g & 1) * 8;
                uint32_t addr = bs_base + (uint32_t)(buf * GBN * GST + n * GST + col) * 2u;
                asm volatile("ldmatrix.sync.aligned.m8n8.x4.shared.b16 {%0,%1,%2,%3}, [%4];\n"
                             : "=r"(b[bt][0]), "=r"(b[bt][1]), "=r"(b[bt][2]), "=r"(b[bt][3])
                             : "r"(addr));
            }
#pragma unroll
            for (int mt = 0; mt < 4; ++mt) {
#pragma unroll
                for (int nt = 0; nt < 4; ++nt) {
                    uint32_t b0 = b[nt >> 1][(nt & 1) * 2];
                    uint32_t b1 = b[nt >> 1][(nt & 1) * 2 + 1];
                    asm volatile(
                        "mma.sync.aligned.m16n8k16.row.col.f32.f16.f16.f32 "
                        "{%0,%1,%2,%3}, {%4,%5,%6,%7}, {%8,%9}, {%0,%1,%2,%3};\n"
                        : "+f"(acc[mt][nt][0]), "+f"(acc[mt][nt][1]),
                          "+f"(acc[mt][nt][2]), "+f"(acc[mt][nt][3])
                        : "r"(a[mt][0]), "r"(a[mt][1]), "r"(a[mt][2]), "r"(a[mt][3]),
                          "r"(b0), "r"(b1));
                }
            }
        }
    };

    // ---- pipelined main loop (exact R3) ----
    const int NT = IN_F / GBK;   // 128
    load_tile(0, 0);
    asm volatile("cp.async.commit_group;\n");
    asm volatile("cp.async.wait_group 0;\n");
    __syncthreads();

    for (int kt = 0; kt < NT; ++kt) {
        int cur = kt & 1;
        if (kt + 1 < NT) {
            load_tile(kt + 1, cur ^ 1);
            asm volatile("cp.async.commit_group;\n");
        }
        compute(cur);
        if (kt + 1 < NT) asm volatile("cp.async.wait_group 0;\n");
        __syncthreads();
    }

    // ---- epilogue: + bias, fp32 store ----
#pragma unroll
    for (int nt = 0; nt < 4; ++nt) {
        int c0 = bn * GBN + wn * 32 + nt * 8 + (lane & 3) * 2;
        float b0 = bias[c0], b1 = bias[c0 + 1];
#pragma unroll
        for (int mt = 0; mt < 4; ++mt) {
            int r0 = bm * GBM + wm * 64 + mt * 16 + (lane >> 2);
            float2 v0 = make_float2(acc[mt][nt][0] + b0, acc[mt][nt][1] + b1);
            float2 v1 = make_float2(acc[mt][nt][2] + b0, acc[mt][nt][3] + b1);
            *reinterpret_cast<float2*>(out + (size_t)r0 * OUT_F + c0)       = v0;
            *reinterpret_cast<float2*>(out + (size_t)(r0 + 8) * OUT_F + c0) = v1;
        }
    }
}

// ============================================================================
// launch
// ============================================================================
extern "C" void kernel_launch(void* const* d_in, const int* in_sizes, int n_in,
                              void* d_out, int out_size) {
    const float* x    = (const float*)d_in[0];
    const void*  pw   = (const void*)d_in[1];
    const void*  s_w  = (const void*)d_in[2];
    const float* bias = (const float*)d_in[3];
    float*       out  = (float*)d_out;

    detect_kernel<<<1, 1>>>(s_w, pw);
    quantile_kernel<<<IN_F / 64, 256>>>(x);
    quant_x_kernel<<<(TOKENS * IN_F / 8) / 256, 256>>>(x);
    dequant_w_kernel<<<(OUT_F * (IN_F / 2) / 8) / 256, 256>>>(pw, s_w);
    gemm_kernel<<<dim3(OUT_F / GBN, TOKENS / GBM), 256>>>(bias, out);
}